// round 8
// baseline (speedup 1.0000x reference)
#include <cuda_runtime.h>
#include <cstdint>

#define NB 16
#define NA 200000
#define NK 300
#define NKP 320        // padded box array (lane reads up to wi*32+31 = 319)
#define CAP 16384
#define FCAP 2048
#define NW 10          // ceil(300/32) mask words
#define NBINS 2048
#define FULLM 0xffffffffu
#define BLKS_PER_B 20
#define F4_PER_BLK 2500   // 20 * 2500 float4 = 50000 f4 = 200000 elems = one batch

typedef unsigned long long ull;

// Scratch (no allocations). All zero-init at module load; the select phase
// re-zeroes everything it used so graph replays are identical.
__device__ int g_count[NB];
__device__ int g_done[NB];
__device__ unsigned g_hist[NB][NBINS];
__device__ ull g_cand[NB * CAP];

__device__ __forceinline__ int bin_of(unsigned sbits) {
    return min((int)((sbits >> 12) - 0x3F000u), NBINS - 1);
}

__device__ __forceinline__ void bitonic_desc(ull* a, int N, int tid) {
    for (int k = 2; k <= N; k <<= 1) {
        for (int j = k >> 1; j > 0; j >>= 1) {
            for (int i = tid; i < N; i += 1024) {
                int ixj = i ^ j;
                if (ixj > i) {
                    ull a0 = a[i], a1 = a[ixj];
                    bool up = ((i & k) == 0);
                    if ((a0 < a1) == up) { a[i] = a1; a[ixj] = a0; }
                }
            }
            __syncthreads();
        }
    }
}

// ---------------------------------------------------------------------------
// Fused kernel. 320 blocks x 1024 threads, 20 blocks per batch.
// Phase 1 (all blocks): scan 10000 conf elems; sigmoid(x)>=0.5 <=> x>=0;
//   stage candidate keys in smem; one atomicAdd to g_count per block; copy to
//   g_cand; build global score histogram; fence; arrive on g_done[b].
// Phase 2 (last arriver per batch only): suffix-scan hist (rank 300) ->
//   ballot compact -> split counting-rank sort -> decode -> triangular IoU
//   masks -> fixed-point greedy NMS -> outputs -> reset scratch.
// ---------------------------------------------------------------------------
__global__ void __launch_bounds__(1024, 1)
k_fused(const float4* __restrict__ conf4,
        const float* __restrict__ p_loc,
        const float* __restrict__ anchors,
        float* __restrict__ out) {
    __shared__ __align__(16) ull cand2[FCAP];   // 16 KB: staging (scan) / compact buf (select)
    __shared__ int scnt, sbase, s_last;
    __shared__ unsigned wsum[32];
    __shared__ int sT, scount2, schanged;
    __shared__ int srank_hi[512];               // 2 KB
    __shared__ ull sstage[NK];                  // 2.4 KB
    __shared__ float4 sbox[NKP];                // 5.12 KB
    __shared__ float sarea[NKP];                // 1.28 KB
    __shared__ float ssc[NK];                   // 1.2 KB
    __shared__ unsigned colmask[NK * NW];       // 12 KB (triangular part only)
    __shared__ unsigned svalid[NW];
    __shared__ unsigned kw[2][NW];

    const int tid = threadIdx.x;
    const int lane = tid & 31;
    const int wrp = tid >> 5;
    const unsigned ltm = (1u << lane) - 1u;
    const int b = blockIdx.x / BLKS_PER_B;
    const int c = blockIdx.x % BLKS_PER_B;

    if (tid == 0) scnt = 0;
    __syncthreads();

    // ---------------- Phase 1: scan ----------------
    {
        int base4 = b * (NA / 4) + c * F4_PER_BLK;
        for (int k = tid; k < F4_PER_BLK; k += 1024) {
            int gi = base4 + k;
            float4 v = conf4[gi];
            int e0 = gi * 4 - b * NA;            // anchor index of v.x
            float xs[4] = {v.x, v.y, v.z, v.w};
            #pragma unroll
            for (int e = 0; e < 4; e++) {
                if (xs[e] >= 0.0f) {
                    float s = 1.0f / (1.0f + expf(-xs[e]));
                    unsigned sbits = __float_as_uint(s);
                    ull key = ((ull)sbits << 32) |
                              (ull)(0xFFFFFFFFu - (unsigned)(e0 + e));  // low idx wins ties
                    int p = atomicAdd(&scnt, 1);
                    if (p < FCAP) cand2[p] = key;
                    atomicAdd(&g_hist[b][bin_of(sbits)], 1u);
                }
            }
        }
        __syncthreads();
        int n = min(scnt, FCAP);
        if (tid == 0) sbase = (n > 0) ? atomicAdd(&g_count[b], n) : 0;
        __syncthreads();
        int gbase = sbase;
        for (int i = tid; i < n; i += 1024) {
            int p = gbase + i;
            if (p < CAP) g_cand[b * CAP + p] = cand2[i];
        }
    }

    // Release: all threads' global writes, then one arrival per block.
    __threadfence();
    __syncthreads();
    if (tid == 0) {
        int arrived = atomicAdd(&g_done[b], 1);
        s_last = (arrived == BLKS_PER_B - 1);
    }
    __syncthreads();
    if (!s_last) return;
    __threadfence();   // acquire: make peer blocks' g_cand/g_hist writes visible

    // ---------------- Phase 2: select (one block per batch) ----------------
    int count = g_count[b];
    if (count > CAP) count = CAP;

    if (tid < NK) sstage[tid] = 0ULL;
    if (tid >= NK && tid < NKP) {               // pad entries 300..319
        sbox[tid] = make_float4(0.f, 0.f, 0.f, 0.f);
        sarea[tid] = 0.f;
    }
    if (tid == 0) { sT = 0; scount2 = 0; }

    // Suffix scan over histogram (2 bins/thread, reverse order) -> rank-NK bin.
    {
        int r0 = 2 * tid, r1 = 2 * tid + 1;
        unsigned h0 = g_hist[b][NBINS - 1 - r0];
        unsigned h1 = g_hist[b][NBINS - 1 - r1];
        unsigned tsum = h0 + h1;
        unsigned inc = tsum;
        #pragma unroll
        for (int o = 1; o < 32; o <<= 1) {
            unsigned nn = __shfl_up_sync(FULLM, inc, o);
            if (lane >= o) inc += nn;
        }
        if (lane == 31) wsum[wrp] = inc;
        __syncthreads();
        if (tid < 32) {
            unsigned w = wsum[tid];
            #pragma unroll
            for (int o = 1; o < 32; o <<= 1) {
                unsigned nn = __shfl_up_sync(FULLM, w, o);
                if (tid >= o) w += nn;
            }
            wsum[tid] = w;
        }
        __syncthreads();
        unsigned C0 = (wrp ? wsum[wrp - 1] : 0u) + (inc - tsum);
        unsigned C1 = C0 + h0;
        if (C0 < NK && C0 + h0 >= NK) sT = NBINS - 1 - r0;
        if (C1 < NK && C1 + h1 >= NK) sT = NBINS - 1 - r1;
    }
    __syncthreads();

    // Compact bin >= T with warp-aggregated atomics.
    {
        int T = sT;
        int countP = (count + 1023) & ~1023;
        for (int i = tid; i < countP; i += 1024) {
            ull k = 0; bool pred = false;
            if (i < count) {
                k = g_cand[b * CAP + i];
                pred = (bin_of((unsigned)(k >> 32)) >= T);
            }
            unsigned m = __ballot_sync(FULLM, pred);
            if (pred) {
                int leader = __ffs(m) - 1;
                int base = 0;
                if (lane == leader) base = atomicAdd(&scount2, __popc(m));
                base = __shfl_sync(m, base, leader);
                int p = base + __popc(m & ltm);
                if (p < FCAP) cand2[p] = k;
            }
        }
    }
    __syncthreads();
    int count2 = min(scount2, FCAP);

    // Sort by counting-rank (keys unique by construction).
    if (count2 <= 512) {
        // Split comparisons: thread t counts [0,half), thread t+512 counts [half,count2).
        int half = count2 >> 1;
        ull my = 0; int rlo = 0;
        if (tid < count2) {
            my = cand2[tid];
            for (int j = 0; j < half; j++) rlo += (cand2[j] > my);
        } else if (tid >= 512 && tid < 512 + count2) {
            ull m2 = cand2[tid - 512];
            int r = 0;
            for (int j = half; j < count2; j++) r += (cand2[j] > m2);
            srank_hi[tid - 512] = r;
        }
        __syncthreads();
        if (tid < count2) {
            int r = rlo + srank_hi[tid];
            if (r < NK) sstage[r] = my;
        }
        __syncthreads();
    } else if (count2 <= 1024) {
        if (tid < count2) {
            ull my = cand2[tid];
            int r = 0;
            for (int j = 0; j < count2; j++) r += (cand2[j] > my);
            if (r < NK) sstage[r] = my;
        }
        __syncthreads();
    } else {
        int N2 = 2048;                          // count2 <= FCAP == 2048
        for (int i = count2 + tid; i < N2; i += 1024) cand2[i] = 0ULL;
        __syncthreads();
        bitonic_desc(cand2, N2, tid);
        if (tid < NK) sstage[tid] = cand2[tid];
        __syncthreads();
    }

    // Decode boxes for top-K slots; svalid via ballot.
    {
        bool valid = false;
        float x1 = 0.f, y1 = 0.f, x2 = 0.f, y2 = 0.f, s = 0.f, area = 0.f;
        if (tid < NK) {
            ull key = sstage[tid];
            s = __uint_as_float((unsigned)(key >> 32));
            valid = (key != 0ULL);              // real keys have s >= 0.5
            if (valid) {
                int a = (int)(0xFFFFFFFFu - (unsigned)(key & 0xFFFFFFFFu));
                float4 an = ((const float4*)anchors)[a];
                float4 lv = ((const float4*)p_loc)[(size_t)b * NA + a];
                float cx = an.x + lv.x * 0.1f * an.z;
                float cy = an.y + lv.y * 0.1f * an.w;
                float w = an.z * expf(lv.z * 0.2f);
                float h = an.w * expf(lv.w * 0.2f);
                x1 = cx - 0.5f * w; y1 = cy - 0.5f * h;
                x2 = cx + 0.5f * w; y2 = cy + 0.5f * h;
                area = fmaxf(x2 - x1, 0.f) * fmaxf(y2 - y1, 0.f);
            }
        }
        unsigned vb = __ballot_sync(FULLM, valid);
        if (lane == 0 && wrp < NW) svalid[wrp] = vb;
        if (tid < NK) {
            sbox[tid] = make_float4(x1, y1, x2, y2);
            sarea[tid] = area;
            ssc[tid] = s;
        }
    }
    __syncthreads();

    // Triangular suppressor masks: warp handles rows j = wrp, wrp+32, ...
    // Only words wi <= j>>5 can contain suppressors (i < j).
    for (int j = wrp; j < NK; j += 32) {
        float4 bj = sbox[j];
        float ja = sarea[j];
        int wmax = j >> 5;
        for (int wi = 0; wi <= wmax; wi++) {
            int i = wi * 32 + lane;              // <= 319, padded range
            float4 bi = sbox[i];
            float lt0 = fmaxf(bi.x, bj.x), lt1 = fmaxf(bi.y, bj.y);
            float rb0 = fminf(bi.z, bj.z), rb1 = fminf(bi.w, bj.w);
            float iw = fmaxf(rb0 - lt0, 0.f), ih = fmaxf(rb1 - lt1, 0.f);
            float inter = iw * ih;
            float uni = fmaxf(sarea[i] + ja - inter, 1e-9f);
            bool sup = (i < j) && (inter > 0.3f * uni);
            unsigned m = __ballot_sync(FULLM, sup);
            if (lane == 0) colmask[j * NW + wi] = m;
        }
    }
    __syncthreads();

    // Parallel greedy NMS: fixed point of keep[j] = valid[j] & !exists(i<j kept, sup(i,j)).
    {
        if (tid < NW) kw[0][tid] = svalid[tid];
        __syncthreads();
        int cur = 0;
        bool myvalid = (tid < NK) && ((svalid[tid >> 5] >> (tid & 31)) & 1u);
        int mywmax = tid >> 5;
        for (int t = 0; t < NK + 2; t++) {
            if (tid == 0) schanged = 0;
            __syncthreads();
            bool kp = false;
            if (tid < NK) {
                unsigned sup = 0;
                for (int w = 0; w <= mywmax; w++)
                    sup |= colmask[tid * NW + w] & kw[cur][w];
                kp = myvalid && (sup == 0);
            }
            unsigned word = __ballot_sync(FULLM, kp);
            if (lane == 0 && wrp < NW) {
                kw[cur ^ 1][wrp] = word;
                if (word != kw[cur][wrp]) schanged = 1;
            }
            __syncthreads();
            if (!schanged) break;               // fixed point == greedy result
            cur ^= 1;
        }
        if (tid < NW) svalid[tid] = kw[cur][tid];
    }
    __syncthreads();

    // Outputs: [ids(4800) | boxes(19200) | labels(4800) | scores(4800) | keep(4800)]
    if (tid < NK) {
        bool keep = (svalid[tid >> 5] >> (tid & 31)) & 1u;
        int slot = b * NK + tid;
        float kf = keep ? 1.0f : 0.0f;
        float4 bx = sbox[tid];
        out[slot] = keep ? (float)b : -1.0f;
        float* ob = out + NB * NK + slot * 4;
        ob[0] = bx.x * kf;
        ob[1] = bx.y * kf;
        ob[2] = bx.z * kf;
        ob[3] = bx.w * kf;
        out[NB * NK * 5 + slot] = kf;
        out[NB * NK * 6 + slot] = ssc[tid] * kf;
        out[NB * NK * 7 + slot] = kf;
    }

    // Reset global scratch for next replay (module-load values also 0).
    for (int i = tid; i < NBINS; i += 1024) g_hist[b][i] = 0u;
    if (tid == 0) { g_count[b] = 0; g_done[b] = 0; }
}

extern "C" void kernel_launch(void* const* d_in, const int* in_sizes, int n_in,
                              void* d_out, int out_size) {
    const float* p_loc   = (const float*)d_in[0];
    const float* p_conf  = (const float*)d_in[1];
    // d_in[2] = p_landms: dead compute in reference, intentionally unread.
    const float* anchors = (const float*)d_in[3];
    float* out = (float*)d_out;

    k_fused<<<NB * BLKS_PER_B, 1024>>>((const float4*)p_conf, p_loc, anchors, out);
}

// round 10
// speedup vs baseline: 1.0661x; 1.0661x over previous
#include <cuda_runtime.h>
#include <cstdint>

#define NB 16
#define NA 200000
#define NK 300
#define NKP 320        // padded box array (lane reads up to wi*32+31 = 319)
#define CAP 16384
#define FCAP 2048
#define NW 10          // ceil(300/32) mask words
#define NBINS 2048
#define FULLM 0xffffffffu
#define BLKS_PER_B 8
#define F4_PER_BLK 6250      // 8 * 6250 float4 = 200000 elems = one batch
#define F4_PER_BLK_PAD 7168  // 7 * 1024: uniform trip count for warp collectives

typedef unsigned long long ull;

// Scratch (no allocations). All zero-init at module load; the select phase
// re-zeroes everything it used so graph replays are identical.
__device__ int g_count[NB];
__device__ int g_done[NB];
__device__ unsigned g_hist[NB][NBINS];
__device__ ull g_cand[NB * CAP];

__device__ __forceinline__ int bin_of(unsigned sbits) {
    return min((int)((sbits >> 12) - 0x3F000u), NBINS - 1);
}

__device__ __forceinline__ void bitonic_desc(ull* a, int N, int tid) {
    for (int k = 2; k <= N; k <<= 1) {
        for (int j = k >> 1; j > 0; j >>= 1) {
            for (int i = tid; i < N; i += 1024) {
                int ixj = i ^ j;
                if (ixj > i) {
                    ull a0 = a[i], a1 = a[ixj];
                    bool up = ((i & k) == 0);
                    if ((a0 < a1) == up) { a[i] = a1; a[ixj] = a0; }
                }
            }
            __syncthreads();
        }
    }
}

// ---------------------------------------------------------------------------
// Fused kernel. 128 blocks x 1024 threads (ONE wave on 148 SMs), 8 per batch.
// Phase 1 (all blocks): scan 25000 conf elems (padded uniform loop);
//   sigmoid(x)>=0.5 <=> x>=0; warp-aggregated staging into smem; one
//   atomicAdd to g_count per block; copy to g_cand; global histogram;
//   fence; arrive on g_done[b].
// Phase 2 (last arriver per batch): suffix-scan hist (rank 300) -> ballot
//   compact -> split counting-rank sort -> decode -> triangular IoU masks ->
//   fixed-point greedy NMS -> outputs -> reset scratch.
// ---------------------------------------------------------------------------
__global__ void __launch_bounds__(1024, 1)
k_fused(const float4* __restrict__ conf4,
        const float* __restrict__ p_loc,
        const float* __restrict__ anchors,
        float* __restrict__ out) {
    __shared__ __align__(16) ull cand2[FCAP];   // 16 KB: staging (scan) / compact buf (select)
    __shared__ int scnt, sbase, s_last;
    __shared__ unsigned wsum[32];
    __shared__ int sT, scount2, schanged;
    __shared__ int srank_hi[512];               // 2 KB
    __shared__ ull sstage[NK];                  // 2.4 KB
    __shared__ float4 sbox[NKP];                // 5.12 KB
    __shared__ float sarea[NKP];                // 1.28 KB
    __shared__ float ssc[NK];                   // 1.2 KB
    __shared__ unsigned colmask[NK * NW];       // 12 KB (triangular part only)
    __shared__ unsigned svalid[NW];
    __shared__ unsigned kw[2][NW];

    const int tid = threadIdx.x;
    const int lane = tid & 31;
    const int wrp = tid >> 5;
    const unsigned ltm = (1u << lane) - 1u;
    const int b = blockIdx.x / BLKS_PER_B;      // blocks are batch-aligned
    const int c = blockIdx.x % BLKS_PER_B;

    if (tid == 0) scnt = 0;
    __syncthreads();

    // ---------------- Phase 1: scan (uniform trip count, warp-aggregated) ----
    {
        int base4 = b * (NA / 4) + c * F4_PER_BLK;
        for (int k = tid; k < F4_PER_BLK_PAD; k += 1024) {
            bool inb = (k < F4_PER_BLK);
            float4 v = make_float4(-1.f, -1.f, -1.f, -1.f);
            if (inb) v = conf4[base4 + k];
            int e0 = (base4 + k) * 4 - b * NA;   // anchor index of v.x
            float xs[4] = {v.x, v.y, v.z, v.w};
            #pragma unroll
            for (int e = 0; e < 4; e++) {
                bool pred = (xs[e] >= 0.0f);     // false for padded lanes
                unsigned m = __ballot_sync(FULLM, pred);
                if (pred) {
                    float s = 1.0f / (1.0f + expf(-xs[e]));
                    unsigned sbits = __float_as_uint(s);
                    ull key = ((ull)sbits << 32) |
                              (ull)(0xFFFFFFFFu - (unsigned)(e0 + e));  // low idx wins ties
                    int leader = __ffs(m) - 1;
                    int base = 0;
                    if (lane == leader) base = atomicAdd(&scnt, __popc(m));
                    base = __shfl_sync(m, base, leader);
                    int p = base + __popc(m & ltm);
                    if (p < FCAP) cand2[p] = key;
                    atomicAdd(&g_hist[b][bin_of(sbits)], 1u);
                }
            }
        }
        __syncthreads();
        int n = min(scnt, FCAP);
        if (tid == 0) sbase = (n > 0) ? atomicAdd(&g_count[b], n) : 0;
        __syncthreads();
        int gbase = sbase;
        for (int i = tid; i < n; i += 1024) {
            int p = gbase + i;
            if (p < CAP) g_cand[b * CAP + p] = cand2[i];
        }
    }

    // Release: all threads' global writes, then one arrival per block.
    __threadfence();
    __syncthreads();
    if (tid == 0) {
        int arrived = atomicAdd(&g_done[b], 1);
        s_last = (arrived == BLKS_PER_B - 1);
    }
    __syncthreads();
    if (!s_last) return;
    __threadfence();   // acquire: peer blocks' g_cand/g_hist writes now visible

    // ---------------- Phase 2: select (one block per batch) ----------------
    int count = g_count[b];
    if (count > CAP) count = CAP;

    if (tid < NK) sstage[tid] = 0ULL;
    if (tid >= NK && tid < NKP) {               // pad entries 300..319
        sbox[tid] = make_float4(0.f, 0.f, 0.f, 0.f);
        sarea[tid] = 0.f;
    }
    if (tid == 0) { sT = 0; scount2 = 0; }

    // Suffix scan over histogram (2 bins/thread, reverse order) -> rank-NK bin.
    {
        int r0 = 2 * tid, r1 = 2 * tid + 1;
        unsigned h0 = g_hist[b][NBINS - 1 - r0];
        unsigned h1 = g_hist[b][NBINS - 1 - r1];
        unsigned tsum = h0 + h1;
        unsigned inc = tsum;
        #pragma unroll
        for (int o = 1; o < 32; o <<= 1) {
            unsigned nn = __shfl_up_sync(FULLM, inc, o);
            if (lane >= o) inc += nn;
        }
        if (lane == 31) wsum[wrp] = inc;
        __syncthreads();
        if (tid < 32) {
            unsigned w = wsum[tid];
            #pragma unroll
            for (int o = 1; o < 32; o <<= 1) {
                unsigned nn = __shfl_up_sync(FULLM, w, o);
                if (tid >= o) w += nn;
            }
            wsum[tid] = w;
        }
        __syncthreads();
        unsigned C0 = (wrp ? wsum[wrp - 1] : 0u) + (inc - tsum);
        unsigned C1 = C0 + h0;
        if (C0 < NK && C0 + h0 >= NK) sT = NBINS - 1 - r0;
        if (C1 < NK && C1 + h1 >= NK) sT = NBINS - 1 - r1;
    }
    __syncthreads();

    // Compact bin >= T with warp-aggregated atomics (padded uniform loop).
    {
        int T = sT;
        int countP = (count + 1023) & ~1023;
        for (int i = tid; i < countP; i += 1024) {
            ull k = 0; bool pred = false;
            if (i < count) {
                k = g_cand[b * CAP + i];
                pred = (bin_of((unsigned)(k >> 32)) >= T);
            }
            unsigned m = __ballot_sync(FULLM, pred);
            if (pred) {
                int leader = __ffs(m) - 1;
                int base = 0;
                if (lane == leader) base = atomicAdd(&scount2, __popc(m));
                base = __shfl_sync(m, base, leader);
                int p = base + __popc(m & ltm);
                if (p < FCAP) cand2[p] = k;
            }
        }
    }
    __syncthreads();
    int count2 = min(scount2, FCAP);

    // Sort by counting-rank (keys unique by construction).
    if (count2 <= 512) {
        // Split comparisons: thread t counts [0,half), thread t+512 counts [half,count2).
        int half = count2 >> 1;
        ull my = 0; int rlo = 0;
        if (tid < count2) {
            my = cand2[tid];
            for (int j = 0; j < half; j++) rlo += (cand2[j] > my);
        } else if (tid >= 512 && tid < 512 + count2) {
            ull m2 = cand2[tid - 512];
            int r = 0;
            for (int j = half; j < count2; j++) r += (cand2[j] > m2);
            srank_hi[tid - 512] = r;
        }
        __syncthreads();
        if (tid < count2) {
            int r = rlo + srank_hi[tid];
            if (r < NK) sstage[r] = my;
        }
        __syncthreads();
    } else if (count2 <= 1024) {
        if (tid < count2) {
            ull my = cand2[tid];
            int r = 0;
            for (int j = 0; j < count2; j++) r += (cand2[j] > my);
            if (r < NK) sstage[r] = my;
        }
        __syncthreads();
    } else {
        int N2 = 2048;                          // count2 <= FCAP == 2048
        for (int i = count2 + tid; i < N2; i += 1024) cand2[i] = 0ULL;
        __syncthreads();
        bitonic_desc(cand2, N2, tid);
        if (tid < NK) sstage[tid] = cand2[tid];
        __syncthreads();
    }

    // Decode boxes for top-K slots; svalid via ballot.
    {
        bool valid = false;
        float x1 = 0.f, y1 = 0.f, x2 = 0.f, y2 = 0.f, s = 0.f, area = 0.f;
        if (tid < NK) {
            ull key = sstage[tid];
            s = __uint_as_float((unsigned)(key >> 32));
            valid = (key != 0ULL);              // real keys have s >= 0.5
            if (valid) {
                int a = (int)(0xFFFFFFFFu - (unsigned)(key & 0xFFFFFFFFu));
                float4 an = ((const float4*)anchors)[a];
                float4 lv = ((const float4*)p_loc)[(size_t)b * NA + a];
                float cx = an.x + lv.x * 0.1f * an.z;
                float cy = an.y + lv.y * 0.1f * an.w;
                float w = an.z * expf(lv.z * 0.2f);
                float h = an.w * expf(lv.w * 0.2f);
                x1 = cx - 0.5f * w; y1 = cy - 0.5f * h;
                x2 = cx + 0.5f * w; y2 = cy + 0.5f * h;
                area = fmaxf(x2 - x1, 0.f) * fmaxf(y2 - y1, 0.f);
            }
        }
        unsigned vb = __ballot_sync(FULLM, valid);
        if (lane == 0 && wrp < NW) svalid[wrp] = vb;
        if (tid < NK) {
            sbox[tid] = make_float4(x1, y1, x2, y2);
            sarea[tid] = area;
            ssc[tid] = s;
        }
    }
    __syncthreads();

    // Triangular suppressor masks: warp handles rows j = wrp, wrp+32, ...
    // Only words wi <= j>>5 can contain suppressors (i < j).
    for (int j = wrp; j < NK; j += 32) {
        float4 bj = sbox[j];
        float ja = sarea[j];
        int wmax = j >> 5;
        for (int wi = 0; wi <= wmax; wi++) {
            int i = wi * 32 + lane;              // <= 319, padded range
            float4 bi = sbox[i];
            float lt0 = fmaxf(bi.x, bj.x), lt1 = fmaxf(bi.y, bj.y);
            float rb0 = fminf(bi.z, bj.z), rb1 = fminf(bi.w, bj.w);
            float iw = fmaxf(rb0 - lt0, 0.f), ih = fmaxf(rb1 - lt1, 0.f);
            float inter = iw * ih;
            float uni = fmaxf(sarea[i] + ja - inter, 1e-9f);
            bool sup = (i < j) && (inter > 0.3f * uni);
            unsigned m = __ballot_sync(FULLM, sup);
            if (lane == 0) colmask[j * NW + wi] = m;
        }
    }
    __syncthreads();

    // Parallel greedy NMS: fixed point of keep[j] = valid[j] & !exists(i<j kept, sup(i,j)).
    {
        if (tid < NW) kw[0][tid] = svalid[tid];
        __syncthreads();
        int cur = 0;
        bool myvalid = (tid < NK) && ((svalid[tid >> 5] >> (tid & 31)) & 1u);
        int mywmax = tid >> 5;
        for (int t = 0; t < NK + 2; t++) {
            if (tid == 0) schanged = 0;
            __syncthreads();
            bool kp = false;
            if (tid < NK) {
                unsigned sup = 0;
                for (int w = 0; w <= mywmax; w++)
                    sup |= colmask[tid * NW + w] & kw[cur][w];
                kp = myvalid && (sup == 0);
            }
            unsigned word = __ballot_sync(FULLM, kp);
            if (lane == 0 && wrp < NW) {
                kw[cur ^ 1][wrp] = word;
                if (word != kw[cur][wrp]) schanged = 1;
            }
            __syncthreads();
            if (!schanged) break;               // fixed point == greedy result
            cur ^= 1;
        }
        if (tid < NW) svalid[tid] = kw[cur][tid];
    }
    __syncthreads();

    // Outputs: [ids(4800) | boxes(19200) | labels(4800) | scores(4800) | keep(4800)]
    if (tid < NK) {
        bool keep = (svalid[tid >> 5] >> (tid & 31)) & 1u;
        int slot = b * NK + tid;
        float kf = keep ? 1.0f : 0.0f;
        float4 bx = sbox[tid];
        out[slot] = keep ? (float)b : -1.0f;
        float* ob = out + NB * NK + slot * 4;
        ob[0] = bx.x * kf;
        ob[1] = bx.y * kf;
        ob[2] = bx.z * kf;
        ob[3] = bx.w * kf;
        out[NB * NK * 5 + slot] = kf;
        out[NB * NK * 6 + slot] = ssc[tid] * kf;
        out[NB * NK * 7 + slot] = kf;
    }

    // Reset global scratch for next replay (module-load values also 0).
    for (int i = tid; i < NBINS; i += 1024) g_hist[b][i] = 0u;
    if (tid == 0) { g_count[b] = 0; g_done[b] = 0; }
}

extern "C" void kernel_launch(void* const* d_in, const int* in_sizes, int n_in,
                              void* d_out, int out_size) {
    const float* p_loc   = (const float*)d_in[0];
    const float* p_conf  = (const float*)d_in[1];
    // d_in[2] = p_landms: dead compute in reference, intentionally unread.
    const float* anchors = (const float*)d_in[3];
    float* out = (float*)d_out;

    k_fused<<<NB * BLKS_PER_B, 1024>>>((const float4*)p_conf, p_loc, anchors, out);
}

// round 11
// speedup vs baseline: 1.1293x; 1.0593x over previous
#include <cuda_runtime.h>
#include <cstdint>

#define NB 16
#define NA 200000
#define NK 300
#define NKP 320        // padded box array (lane reads up to wi*32+31 = 319)
#define CAP 16384
#define FCAP 2048
#define NW 10          // ceil(300/32) mask words
#define NBINS 2048
#define FULLM 0xffffffffu
#define BLKS_PER_B 8
#define SEL_BLKS 4           // blocks per batch that run phase 2
#define F4_PER_BLK 6250      // 8 * 6250 float4 = 200000 elems = one batch
#define F4_PER_BLK_PAD 7168  // 7 * 1024: uniform trip count for warp collectives

typedef unsigned long long ull;

// Scratch (no allocations). Zero-init at load; runner block resets per replay.
__device__ int g_count[NB];
__device__ int g_done[NB];
__device__ int g_done2[NB];
__device__ unsigned g_hist[NB][NBINS];
__device__ ull g_cand[NB * CAP];
__device__ unsigned g_mask[NB][NK * NW];   // every used word overwritten each run

__device__ __forceinline__ int bin_of(unsigned sbits) {
    return min((int)((sbits >> 12) - 0x3F000u), NBINS - 1);
}

__device__ __forceinline__ void bitonic_desc(ull* a, int N, int tid) {
    for (int k = 2; k <= N; k <<= 1) {
        for (int j = k >> 1; j > 0; j >>= 1) {
            for (int i = tid; i < N; i += 1024) {
                int ixj = i ^ j;
                if (ixj > i) {
                    ull a0 = a[i], a1 = a[ixj];
                    bool up = ((i & k) == 0);
                    if ((a0 < a1) == up) { a[i] = a1; a[ixj] = a0; }
                }
            }
            __syncthreads();
        }
    }
}

// ---------------------------------------------------------------------------
// Fused cooperative kernel. 128 blocks x 1024 (ONE wave -> co-residency
// guaranteed -> spin-wait safe). 8 blocks/batch scan; 4 run select; 1 runs NMS.
// ---------------------------------------------------------------------------
__global__ void __launch_bounds__(1024, 1)
k_fused(const float4* __restrict__ conf4,
        const float* __restrict__ p_loc,
        const float* __restrict__ anchors,
        float* __restrict__ out) {
    __shared__ __align__(16) ull cand2[FCAP];   // staging (scan) / compact buf (select)
    __shared__ int scnt, sbase, s_flag;
    __shared__ unsigned wsum[32];
    __shared__ int sT, scount2, schanged;
    __shared__ int srank_hi[512];
    __shared__ ull sstage[NK];
    __shared__ float4 sbox[NKP];
    __shared__ float sarea[NKP];
    __shared__ float ssc[NK];
    __shared__ unsigned colmask[NK * NW];
    __shared__ unsigned svalid[NW];
    __shared__ unsigned kw[2][NW];

    const int tid = threadIdx.x;
    const int lane = tid & 31;
    const int wrp = tid >> 5;
    const unsigned ltm = (1u << lane) - 1u;
    const int b = blockIdx.x / BLKS_PER_B;      // blocks are batch-aligned
    const int c = blockIdx.x % BLKS_PER_B;

    if (tid == 0) scnt = 0;
    __syncthreads();

    // ---------------- Phase 1: scan (uniform trip count, warp-aggregated) ----
    {
        int base4 = b * (NA / 4) + c * F4_PER_BLK;
        for (int k = tid; k < F4_PER_BLK_PAD; k += 1024) {
            bool inb = (k < F4_PER_BLK);
            float4 v = make_float4(-1.f, -1.f, -1.f, -1.f);
            if (inb) v = conf4[base4 + k];
            int e0 = (base4 + k) * 4 - b * NA;   // anchor index of v.x
            float xs[4] = {v.x, v.y, v.z, v.w};
            #pragma unroll
            for (int e = 0; e < 4; e++) {
                bool pred = (xs[e] >= 0.0f);     // false for padded lanes
                unsigned m = __ballot_sync(FULLM, pred);
                if (pred) {
                    float s = 1.0f / (1.0f + expf(-xs[e]));
                    unsigned sbits = __float_as_uint(s);
                    ull key = ((ull)sbits << 32) |
                              (ull)(0xFFFFFFFFu - (unsigned)(e0 + e));  // low idx wins ties
                    int leader = __ffs(m) - 1;
                    int base = 0;
                    if (lane == leader) base = atomicAdd(&scnt, __popc(m));
                    base = __shfl_sync(m, base, leader);
                    int p = base + __popc(m & ltm);
                    if (p < FCAP) cand2[p] = key;
                    atomicAdd(&g_hist[b][bin_of(sbits)], 1u);
                }
            }
        }
        __syncthreads();
        int n = min(scnt, FCAP);
        if (tid == 0) sbase = (n > 0) ? atomicAdd(&g_count[b], n) : 0;
        __syncthreads();
        int gbase = sbase;
        for (int i = tid; i < n; i += 1024) {
            int p = gbase + i;
            if (p < CAP) g_cand[b * CAP + p] = cand2[i];
        }
    }

    // Release scan writes; arrive.
    __threadfence();
    __syncthreads();
    if (tid == 0) atomicAdd(&g_done[b], 1);
    if (c >= SEL_BLKS) return;                  // scan-only blocks exit

    // Wait until all 8 scan blocks of this batch arrived (co-resident: safe).
    if (tid == 0) {
        while (atomicAdd(&g_done[b], 0) < BLKS_PER_B) __nanosleep(64);
    }
    __syncthreads();
    __threadfence();   // acquire: peers' g_cand/g_hist writes now visible

    // ---------------- Phase 2: select (4 blocks per batch, redundant front) --
    int count = g_count[b];
    if (count > CAP) count = CAP;

    if (tid < NK) sstage[tid] = 0ULL;
    if (tid >= NK && tid < NKP) {
        sbox[tid] = make_float4(0.f, 0.f, 0.f, 0.f);
        sarea[tid] = 0.f;
    }
    if (tid == 0) { sT = 0; scount2 = 0; }

    // Suffix scan over histogram (2 bins/thread, reverse order) -> rank-NK bin.
    {
        int r0 = 2 * tid, r1 = 2 * tid + 1;
        unsigned h0 = g_hist[b][NBINS - 1 - r0];
        unsigned h1 = g_hist[b][NBINS - 1 - r1];
        unsigned tsum = h0 + h1;
        unsigned inc = tsum;
        #pragma unroll
        for (int o = 1; o < 32; o <<= 1) {
            unsigned nn = __shfl_up_sync(FULLM, inc, o);
            if (lane >= o) inc += nn;
        }
        if (lane == 31) wsum[wrp] = inc;
        __syncthreads();
        if (tid < 32) {
            unsigned w = wsum[tid];
            #pragma unroll
            for (int o = 1; o < 32; o <<= 1) {
                unsigned nn = __shfl_up_sync(FULLM, w, o);
                if (tid >= o) w += nn;
            }
            wsum[tid] = w;
        }
        __syncthreads();
        unsigned C0 = (wrp ? wsum[wrp - 1] : 0u) + (inc - tsum);
        unsigned C1 = C0 + h0;
        if (C0 < NK && C0 + h0 >= NK) sT = NBINS - 1 - r0;
        if (C1 < NK && C1 + h1 >= NK) sT = NBINS - 1 - r1;
    }
    __syncthreads();

    // Compact bin >= T (padded uniform loop, warp-aggregated atomics).
    {
        int T = sT;
        int countP = (count + 1023) & ~1023;
        for (int i = tid; i < countP; i += 1024) {
            ull k = 0; bool pred = false;
            if (i < count) {
                k = g_cand[b * CAP + i];
                pred = (bin_of((unsigned)(k >> 32)) >= T);
            }
            unsigned m = __ballot_sync(FULLM, pred);
            if (pred) {
                int leader = __ffs(m) - 1;
                int base = 0;
                if (lane == leader) base = atomicAdd(&scount2, __popc(m));
                base = __shfl_sync(m, base, leader);
                int p = base + __popc(m & ltm);
                if (p < FCAP) cand2[p] = k;
            }
        }
    }
    __syncthreads();
    int count2 = min(scount2, FCAP);

    // Counting-rank sort (keys unique by construction).
    if (count2 <= 512) {
        int half = count2 >> 1;
        ull my = 0; int rlo = 0;
        if (tid < count2) {
            my = cand2[tid];
            for (int j = 0; j < half; j++) rlo += (cand2[j] > my);
        } else if (tid >= 512 && tid < 512 + count2) {
            ull m2 = cand2[tid - 512];
            int r = 0;
            for (int j = half; j < count2; j++) r += (cand2[j] > m2);
            srank_hi[tid - 512] = r;
        }
        __syncthreads();
        if (tid < count2) {
            int r = rlo + srank_hi[tid];
            if (r < NK) sstage[r] = my;
        }
        __syncthreads();
    } else if (count2 <= 1024) {
        if (tid < count2) {
            ull my = cand2[tid];
            int r = 0;
            for (int j = 0; j < count2; j++) r += (cand2[j] > my);
            if (r < NK) sstage[r] = my;
        }
        __syncthreads();
    } else {
        int N2 = 2048;
        for (int i = count2 + tid; i < N2; i += 1024) cand2[i] = 0ULL;
        __syncthreads();
        bitonic_desc(cand2, N2, tid);
        if (tid < NK) sstage[tid] = cand2[tid];
        __syncthreads();
    }

    // Decode boxes; svalid via ballot. (Identical across the 4 blocks.)
    {
        bool valid = false;
        float x1 = 0.f, y1 = 0.f, x2 = 0.f, y2 = 0.f, s = 0.f, area = 0.f;
        if (tid < NK) {
            ull key = sstage[tid];
            s = __uint_as_float((unsigned)(key >> 32));
            valid = (key != 0ULL);
            if (valid) {
                int a = (int)(0xFFFFFFFFu - (unsigned)(key & 0xFFFFFFFFu));
                float4 an = ((const float4*)anchors)[a];
                float4 lv = ((const float4*)p_loc)[(size_t)b * NA + a];
                float cx = an.x + lv.x * 0.1f * an.z;
                float cy = an.y + lv.y * 0.1f * an.w;
                float w = an.z * expf(lv.z * 0.2f);
                float h = an.w * expf(lv.w * 0.2f);
                x1 = cx - 0.5f * w; y1 = cy - 0.5f * h;
                x2 = cx + 0.5f * w; y2 = cy + 0.5f * h;
                area = fmaxf(x2 - x1, 0.f) * fmaxf(y2 - y1, 0.f);
            }
        }
        unsigned vb = __ballot_sync(FULLM, valid);
        if (lane == 0 && wrp < NW) svalid[wrp] = vb;
        if (tid < NK) {
            sbox[tid] = make_float4(x1, y1, x2, y2);
            sarea[tid] = area;
            ssc[tid] = s;
        }
    }
    __syncthreads();

    // Triangular mask build split 4 ways: this block does rows j%4==c.
    // Warp handles rows j = c + 4*(wrp + 32*k). Words written to global.
    for (int j = c + 4 * wrp; j < NK; j += 128) {
        float4 bj = sbox[j];
        float ja = sarea[j];
        int wmax = j >> 5;
        for (int wi = 0; wi <= wmax; wi++) {
            int i = wi * 32 + lane;              // <= 319, padded range
            float4 bi = sbox[i];
            float lt0 = fmaxf(bi.x, bj.x), lt1 = fmaxf(bi.y, bj.y);
            float rb0 = fminf(bi.z, bj.z), rb1 = fminf(bi.w, bj.w);
            float iw = fmaxf(rb0 - lt0, 0.f), ih = fmaxf(rb1 - lt1, 0.f);
            float inter = iw * ih;
            float uni = fmaxf(sarea[i] + ja - inter, 1e-9f);
            bool sup = (i < j) && (inter > 0.3f * uni);
            unsigned m = __ballot_sync(FULLM, sup);
            if (lane == 0) g_mask[b][j * NW + wi] = m;
        }
    }

    // Release mask writes; last of the 4 runs NMS + output.
    __threadfence();
    __syncthreads();
    if (tid == 0) {
        int a2 = atomicAdd(&g_done2[b], 1);
        s_flag = (a2 == SEL_BLKS - 1);
    }
    __syncthreads();
    if (!s_flag) return;
    __threadfence();   // acquire peers' g_mask writes

    // Pull full mask into smem (triangular words all written; rest unread).
    for (int i = tid; i < NK * NW; i += 1024) colmask[i] = g_mask[b][i];
    __syncthreads();

    // Parallel greedy NMS: fixed point of keep[j] = valid[j] & !exists(i<j kept, sup(i,j)).
    {
        if (tid < NW) kw[0][tid] = svalid[tid];
        __syncthreads();
        int cur = 0;
        bool myvalid = (tid < NK) && ((svalid[tid >> 5] >> (tid & 31)) & 1u);
        int mywmax = tid >> 5;
        for (int t = 0; t < NK + 2; t++) {
            if (tid == 0) schanged = 0;
            __syncthreads();
            bool kp = false;
            if (tid < NK) {
                unsigned sup = 0;
                for (int w = 0; w <= mywmax; w++)
                    sup |= colmask[tid * NW + w] & kw[cur][w];
                kp = myvalid && (sup == 0);
            }
            unsigned word = __ballot_sync(FULLM, kp);
            if (lane == 0 && wrp < NW) {
                kw[cur ^ 1][wrp] = word;
                if (word != kw[cur][wrp]) schanged = 1;
            }
            __syncthreads();
            if (!schanged) break;               // fixed point == greedy result
            cur ^= 1;
        }
        if (tid < NW) svalid[tid] = kw[cur][tid];
    }
    __syncthreads();

    // Outputs: [ids(4800) | boxes(19200) | labels(4800) | scores(4800) | keep(4800)]
    if (tid < NK) {
        bool keep = (svalid[tid >> 5] >> (tid & 31)) & 1u;
        int slot = b * NK + tid;
        float kf = keep ? 1.0f : 0.0f;
        float4 bx = sbox[tid];
        out[slot] = keep ? (float)b : -1.0f;
        float* ob = out + NB * NK + slot * 4;
        ob[0] = bx.x * kf;
        ob[1] = bx.y * kf;
        ob[2] = bx.z * kf;
        ob[3] = bx.w * kf;
        out[NB * NK * 5 + slot] = kf;
        out[NB * NK * 6 + slot] = ssc[tid] * kf;
        out[NB * NK * 7 + slot] = kf;
    }

    // Reset global scratch for next replay (module-load values also 0).
    for (int i = tid; i < NBINS; i += 1024) g_hist[b][i] = 0u;
    if (tid == 0) { g_count[b] = 0; g_done[b] = 0; g_done2[b] = 0; }
}

extern "C" void kernel_launch(void* const* d_in, const int* in_sizes, int n_in,
                              void* d_out, int out_size) {
    const float* p_loc   = (const float*)d_in[0];
    const float* p_conf  = (const float*)d_in[1];
    // d_in[2] = p_landms: dead compute in reference, intentionally unread.
    const float* anchors = (const float*)d_in[3];
    float* out = (float*)d_out;

    k_fused<<<NB * BLKS_PER_B, 1024>>>((const float4*)p_conf, p_loc, anchors, out);
}

// round 12
// speedup vs baseline: 1.3249x; 1.1732x over previous
#include <cuda_runtime.h>
#include <cstdint>

#define NB 16
#define NA 200000
#define NK 300
#define NKP 320        // padded box array (lane reads up to wi*32+31 = 319)
#define CAP 16384
#define FCAP 2048
#define NW 10          // ceil(300/32) mask words
#define NBINS 2048
#define FULLM 0xffffffffu
#define SEL_BLKS 4     // select blocks per batch

typedef unsigned long long ull;

// Scratch (no allocations). Zero-init at load; NMS-runner resets per replay.
__device__ int g_count[NB];
__device__ int g_done2[NB];
__device__ unsigned g_hist[NB][NBINS];
__device__ ull g_cand[NB * CAP];
__device__ unsigned g_mask[NB][NK * NW];   // triangular words rewritten every run

__device__ __forceinline__ int bin_of(unsigned sbits) {
    return min((int)((sbits >> 12) - 0x3F000u), NBINS - 1);
}

// ---------------------------------------------------------------------------
// Pass 1 (R7-proven): streaming scan of p_conf. sigmoid(x)>=0.5 <=> x>=0.
// Precise sigmoid only for positives; per-batch histogram via global RED;
// one compacting atomicAdd per (block, batch).
// ---------------------------------------------------------------------------
__global__ void k_scan(const float4* __restrict__ conf4) {
    __shared__ int scnt[2];
    __shared__ int sbase[2];
    const int t = threadIdx.x;
    if (t < 2) scnt[t] = 0;
    __syncthreads();

    int gi = blockIdx.x * 256 + t;           // float4 index (grid exact: 800000)
    float4 v = conf4[gi];
    int e0 = gi * 4;
    int b0 = (blockIdx.x * 1024) / NA;       // batch of first elem in block
    int split = (b0 + 1) * NA;               // first elem of next batch

    ull key[4]; int pos[4]; int sel[4]; bool pred[4];
    float xs[4] = {v.x, v.y, v.z, v.w};
    #pragma unroll
    for (int e = 0; e < 4; e++) {
        pred[e] = (xs[e] >= 0.0f);
        if (pred[e]) {
            int idx = e0 + e;
            sel[e] = (idx >= split) ? 1 : 0;
            unsigned a = (unsigned)(idx - (b0 + sel[e]) * NA);
            float s = 1.0f / (1.0f + expf(-xs[e]));
            unsigned sbits = __float_as_uint(s);
            key[e] = ((ull)sbits << 32) | (ull)(0xFFFFFFFFu - a);
            pos[e] = atomicAdd(&scnt[sel[e]], 1);
            atomicAdd(&g_hist[b0 + sel[e]][bin_of(sbits)], 1u);
        }
    }
    __syncthreads();
    if (t < 2) sbase[t] = scnt[t] ? atomicAdd(&g_count[b0 + t], scnt[t]) : 0;
    __syncthreads();
    #pragma unroll
    for (int e = 0; e < 4; e++) {
        if (pred[e]) {
            int p = sbase[sel[e]] + pos[e];
            if (p < CAP) g_cand[(b0 + sel[e]) * CAP + p] = key[e];
        }
    }
}

// ---------------------------------------------------------------------------
// Pass 2: 4 blocks per batch (grid = 64).
// Redundant front in all 4: suffix-scan hist (rank 300) -> ballot compact ->
// counting-rank sort -> decode boxes. Mask build split by j%4==c -> g_mask.
// Last arriver: load masks, fixed-point greedy NMS, outputs, reset scratch.
// ---------------------------------------------------------------------------
__device__ __forceinline__ void bitonic_desc(ull* a, int N, int tid) {
    for (int k = 2; k <= N; k <<= 1) {
        for (int j = k >> 1; j > 0; j >>= 1) {
            for (int i = tid; i < N; i += 1024) {
                int ixj = i ^ j;
                if (ixj > i) {
                    ull a0 = a[i], a1 = a[ixj];
                    bool up = ((i & k) == 0);
                    if ((a0 < a1) == up) { a[i] = a1; a[ixj] = a0; }
                }
            }
            __syncthreads();
        }
    }
}

__global__ void __launch_bounds__(1024, 1)
k_select(const float* __restrict__ p_loc,
         const float* __restrict__ anchors,
         float* __restrict__ out) {
    __shared__ __align__(16) ull cand2[FCAP];   // 16 KB
    __shared__ unsigned wsum[32];
    __shared__ int sT, scount2, schanged, s_flag;
    __shared__ int srank_hi[512];
    __shared__ ull sstage[NK];
    __shared__ float4 sbox[NKP];
    __shared__ float sarea[NKP];
    __shared__ float ssc[NK];
    __shared__ unsigned colmask[NK * NW];
    __shared__ unsigned svalid[NW];
    __shared__ unsigned kw[2][NW];

    const int tid = threadIdx.x;
    const int lane = tid & 31;
    const int wrp = tid >> 5;
    const unsigned ltm = (1u << lane) - 1u;
    const int b = blockIdx.x / SEL_BLKS;
    const int c = blockIdx.x % SEL_BLKS;

    int count = g_count[b];
    if (count > CAP) count = CAP;

    if (tid < NK) sstage[tid] = 0ULL;
    if (tid >= NK && tid < NKP) {
        sbox[tid] = make_float4(0.f, 0.f, 0.f, 0.f);
        sarea[tid] = 0.f;
    }
    if (tid == 0) { sT = 0; scount2 = 0; }

    // Suffix scan over histogram (2 bins/thread, reverse order) -> rank-NK bin.
    {
        int r0 = 2 * tid, r1 = 2 * tid + 1;
        unsigned h0 = g_hist[b][NBINS - 1 - r0];
        unsigned h1 = g_hist[b][NBINS - 1 - r1];
        unsigned tsum = h0 + h1;
        unsigned inc = tsum;
        #pragma unroll
        for (int o = 1; o < 32; o <<= 1) {
            unsigned nn = __shfl_up_sync(FULLM, inc, o);
            if (lane >= o) inc += nn;
        }
        if (lane == 31) wsum[wrp] = inc;
        __syncthreads();
        if (tid < 32) {
            unsigned w = wsum[tid];
            #pragma unroll
            for (int o = 1; o < 32; o <<= 1) {
                unsigned nn = __shfl_up_sync(FULLM, w, o);
                if (tid >= o) w += nn;
            }
            wsum[tid] = w;
        }
        __syncthreads();
        unsigned C0 = (wrp ? wsum[wrp - 1] : 0u) + (inc - tsum);
        unsigned C1 = C0 + h0;
        if (C0 < NK && C0 + h0 >= NK) sT = NBINS - 1 - r0;
        if (C1 < NK && C1 + h1 >= NK) sT = NBINS - 1 - r1;
    }
    __syncthreads();

    // Compact bin >= T (padded uniform loop, warp-aggregated atomics).
    {
        int T = sT;
        int countP = (count + 1023) & ~1023;
        for (int i = tid; i < countP; i += 1024) {
            ull k = 0; bool pred = false;
            if (i < count) {
                k = g_cand[b * CAP + i];
                pred = (bin_of((unsigned)(k >> 32)) >= T);
            }
            unsigned m = __ballot_sync(FULLM, pred);
            if (pred) {
                int leader = __ffs(m) - 1;
                int base = 0;
                if (lane == leader) base = atomicAdd(&scount2, __popc(m));
                base = __shfl_sync(m, base, leader);
                int p = base + __popc(m & ltm);
                if (p < FCAP) cand2[p] = k;
            }
        }
    }
    __syncthreads();
    int count2 = min(scount2, FCAP);

    // Counting-rank sort (keys unique by construction).
    if (count2 <= 512) {
        int half = count2 >> 1;
        ull my = 0; int rlo = 0;
        if (tid < count2) {
            my = cand2[tid];
            for (int j = 0; j < half; j++) rlo += (cand2[j] > my);
        } else if (tid >= 512 && tid < 512 + count2) {
            ull m2 = cand2[tid - 512];
            int r = 0;
            for (int j = half; j < count2; j++) r += (cand2[j] > m2);
            srank_hi[tid - 512] = r;
        }
        __syncthreads();
        if (tid < count2) {
            int r = rlo + srank_hi[tid];
            if (r < NK) sstage[r] = my;
        }
        __syncthreads();
    } else if (count2 <= 1024) {
        if (tid < count2) {
            ull my = cand2[tid];
            int r = 0;
            for (int j = 0; j < count2; j++) r += (cand2[j] > my);
            if (r < NK) sstage[r] = my;
        }
        __syncthreads();
    } else {
        int N2 = 2048;
        for (int i = count2 + tid; i < N2; i += 1024) cand2[i] = 0ULL;
        __syncthreads();
        bitonic_desc(cand2, N2, tid);
        if (tid < NK) sstage[tid] = cand2[tid];
        __syncthreads();
    }

    // Decode boxes; svalid via ballot. (Identical in all 4 blocks.)
    {
        bool valid = false;
        float x1 = 0.f, y1 = 0.f, x2 = 0.f, y2 = 0.f, s = 0.f, area = 0.f;
        if (tid < NK) {
            ull key = sstage[tid];
            s = __uint_as_float((unsigned)(key >> 32));
            valid = (key != 0ULL);
            if (valid) {
                int a = (int)(0xFFFFFFFFu - (unsigned)(key & 0xFFFFFFFFu));
                float4 an = ((const float4*)anchors)[a];
                float4 lv = ((const float4*)p_loc)[(size_t)b * NA + a];
                float cx = an.x + lv.x * 0.1f * an.z;
                float cy = an.y + lv.y * 0.1f * an.w;
                float w = an.z * expf(lv.z * 0.2f);
                float h = an.w * expf(lv.w * 0.2f);
                x1 = cx - 0.5f * w; y1 = cy - 0.5f * h;
                x2 = cx + 0.5f * w; y2 = cy + 0.5f * h;
                area = fmaxf(x2 - x1, 0.f) * fmaxf(y2 - y1, 0.f);
            }
        }
        unsigned vb = __ballot_sync(FULLM, valid);
        if (lane == 0 && wrp < NW) svalid[wrp] = vb;
        if (tid < NK) {
            sbox[tid] = make_float4(x1, y1, x2, y2);
            sarea[tid] = area;
            ssc[tid] = s;
        }
    }
    __syncthreads();

    // Triangular mask build split 4 ways: this block does rows j%4==c.
    for (int j = c + 4 * wrp; j < NK; j += 128) {
        float4 bj = sbox[j];
        float ja = sarea[j];
        int wmax = j >> 5;
        for (int wi = 0; wi <= wmax; wi++) {
            int i = wi * 32 + lane;              // <= 319, padded range
            float4 bi = sbox[i];
            float lt0 = fmaxf(bi.x, bj.x), lt1 = fmaxf(bi.y, bj.y);
            float rb0 = fminf(bi.z, bj.z), rb1 = fminf(bi.w, bj.w);
            float iw = fmaxf(rb0 - lt0, 0.f), ih = fmaxf(rb1 - lt1, 0.f);
            float inter = iw * ih;
            float uni = fmaxf(sarea[i] + ja - inter, 1e-9f);
            bool sup = (i < j) && (inter > 0.3f * uni);
            unsigned m = __ballot_sync(FULLM, sup);
            if (lane == 0) g_mask[b][j * NW + wi] = m;
        }
    }

    // Release mask writes; last of 4 runs NMS + output.
    __threadfence();
    __syncthreads();
    if (tid == 0) {
        int a2 = atomicAdd(&g_done2[b], 1);
        s_flag = (a2 == SEL_BLKS - 1);
    }
    __syncthreads();
    if (!s_flag) return;
    __threadfence();   // acquire peers' g_mask writes

    // Pull masks into smem (only triangular words are read below).
    for (int i = tid; i < NK * NW; i += 1024) colmask[i] = g_mask[b][i];
    __syncthreads();

    // Parallel greedy NMS: fixed point of keep[j] = valid[j] & !exists(i<j kept, sup(i,j)).
    {
        if (tid < NW) kw[0][tid] = svalid[tid];
        __syncthreads();
        int cur = 0;
        bool myvalid = (tid < NK) && ((svalid[tid >> 5] >> (tid & 31)) & 1u);
        int mywmax = tid >> 5;
        for (int t = 0; t < NK + 2; t++) {
            if (tid == 0) schanged = 0;
            __syncthreads();
            bool kp = false;
            if (tid < NK) {
                unsigned sup = 0;
                for (int w = 0; w <= mywmax; w++)
                    sup |= colmask[tid * NW + w] & kw[cur][w];
                kp = myvalid && (sup == 0);
            }
            unsigned word = __ballot_sync(FULLM, kp);
            if (lane == 0 && wrp < NW) {
                kw[cur ^ 1][wrp] = word;
                if (word != kw[cur][wrp]) schanged = 1;
            }
            __syncthreads();
            if (!schanged) break;               // fixed point == greedy result
            cur ^= 1;
        }
        if (tid < NW) svalid[tid] = kw[cur][tid];
    }
    __syncthreads();

    // Outputs: [ids(4800) | boxes(19200) | labels(4800) | scores(4800) | keep(4800)]
    if (tid < NK) {
        bool keep = (svalid[tid >> 5] >> (tid & 31)) & 1u;
        int slot = b * NK + tid;
        float kf = keep ? 1.0f : 0.0f;
        float4 bx = sbox[tid];
        out[slot] = keep ? (float)b : -1.0f;
        float* ob = out + NB * NK + slot * 4;
        ob[0] = bx.x * kf;
        ob[1] = bx.y * kf;
        ob[2] = bx.z * kf;
        ob[3] = bx.w * kf;
        out[NB * NK * 5 + slot] = kf;
        out[NB * NK * 6 + slot] = ssc[tid] * kf;
        out[NB * NK * 7 + slot] = kf;
    }

    // Reset global scratch for next replay (module-load values also 0).
    for (int i = tid; i < NBINS; i += 1024) g_hist[b][i] = 0u;
    if (tid == 0) { g_count[b] = 0; g_done2[b] = 0; }
}

extern "C" void kernel_launch(void* const* d_in, const int* in_sizes, int n_in,
                              void* d_out, int out_size) {
    const float* p_loc   = (const float*)d_in[0];
    const float* p_conf  = (const float*)d_in[1];
    // d_in[2] = p_landms: dead compute in reference, intentionally unread.
    const float* anchors = (const float*)d_in[3];
    float* out = (float*)d_out;

    k_scan<<<(NB * NA / 4) / 256, 256>>>((const float4*)p_conf);
    k_select<<<NB * SEL_BLKS, 1024>>>(p_loc, anchors, out);
}